// round 2
// baseline (speedup 1.0000x reference)
#include <cuda_runtime.h>
#include <math.h>

#define N_TOK 16384
#define D 512
#define SEQL 1024
#define BSZ 16
#define DFF 2048
#define ATT_SCALE 0.125f

// -------------------- scratch (__device__ globals; no allocation) --------------------
__device__ float d_M1[D * D];                       // fc_c @ wq_c
__device__ float d_M3[D * D];                       // fc_x @ wq_x
__device__ float d_Kg[(size_t)N_TOK * D];
__device__ float d_Vg[(size_t)N_TOK * D];
__device__ float d_B0[(size_t)N_TOK * D];           // xc -> g
__device__ float d_B1[(size_t)N_TOK * D];           // u -> att -> y
__device__ float d_B2[(size_t)N_TOK * D];           // x1 -> h
__device__ float d_B3[(size_t)N_TOK * D];           // x2c -> x2
__device__ float d_B4[(size_t)N_TOK * D];           // Q -> x3
__device__ float d_hid[(size_t)N_TOK * DFF];        // MLP hidden

// -------------------- GEMM: C[MxN] = act(A[MxK] @ B[NxK]^T + bias) --------------------
// BM=BN=64, BK=16, 256 threads, 4x4 microtile. M,N mult of 64; K mult of 16.
__global__ __launch_bounds__(256) void gemm_tn(
    float* __restrict__ C, const float* __restrict__ A, const float* __restrict__ B,
    int M, int N, int K, const float* __restrict__ bias, int act)
{
    __shared__ float As[16][64];
    __shared__ float Bs[16][64];
    const int tid = threadIdx.x;
    const int tx = tid & 15, ty = tid >> 4;
    const int lr = tid >> 2, lc = (tid & 3) << 2;
    const float* Ab = A + (size_t)blockIdx.y * 64 * K;
    const float* Bb = B + (size_t)blockIdx.x * 64 * K;
    float acc[4][4] = {};
    for (int k0 = 0; k0 < K; k0 += 16) {
        float4 a4 = *(const float4*)(Ab + (size_t)lr * K + k0 + lc);
        float4 b4 = *(const float4*)(Bb + (size_t)lr * K + k0 + lc);
        __syncthreads();
        As[lc + 0][lr] = a4.x; As[lc + 1][lr] = a4.y; As[lc + 2][lr] = a4.z; As[lc + 3][lr] = a4.w;
        Bs[lc + 0][lr] = b4.x; Bs[lc + 1][lr] = b4.y; Bs[lc + 2][lr] = b4.z; Bs[lc + 3][lr] = b4.w;
        __syncthreads();
        #pragma unroll
        for (int k = 0; k < 16; k++) {
            float4 av = *(const float4*)&As[k][ty << 2];
            float4 bv = *(const float4*)&Bs[k][tx << 2];
            float a[4] = {av.x, av.y, av.z, av.w};
            float b[4] = {bv.x, bv.y, bv.z, bv.w};
            #pragma unroll
            for (int i = 0; i < 4; i++)
                #pragma unroll
                for (int j = 0; j < 4; j++) acc[i][j] += a[i] * b[j];
        }
    }
    #pragma unroll
    for (int i = 0; i < 4; i++) {
        int m = blockIdx.y * 64 + (ty << 2) + i;
        #pragma unroll
        for (int j = 0; j < 4; j++) {
            int n = blockIdx.x * 64 + (tx << 2) + j;
            float v = acc[i][j];
            if (bias) v += bias[n];
            if (act) v = 0.5f * v * (1.0f + erff(v * 0.70710678118654752f));
            C[(size_t)m * N + n] = v;
        }
    }
}

// -------------------- GEMM NN: C[MxN] = A[MxK] @ B[KxN] (for M1/M3 precompute) -------
__global__ __launch_bounds__(256) void gemm_nn(
    float* __restrict__ C, const float* __restrict__ A, const float* __restrict__ B,
    int M, int N, int K)
{
    __shared__ float As[16][64];
    __shared__ float Bs[16][64];
    const int tid = threadIdx.x;
    const int tx = tid & 15, ty = tid >> 4;
    const int lr = tid >> 2, lc = (tid & 3) << 2;
    const int bkr = tid >> 4, bnc = (tid & 15) << 2;
    const float* Ab = A + (size_t)blockIdx.y * 64 * K;
    float acc[4][4] = {};
    for (int k0 = 0; k0 < K; k0 += 16) {
        float4 a4 = *(const float4*)(Ab + (size_t)lr * K + k0 + lc);
        float4 b4 = *(const float4*)(B + (size_t)(k0 + bkr) * N + blockIdx.x * 64 + bnc);
        __syncthreads();
        As[lc + 0][lr] = a4.x; As[lc + 1][lr] = a4.y; As[lc + 2][lr] = a4.z; As[lc + 3][lr] = a4.w;
        *(float4*)&Bs[bkr][bnc] = b4;
        __syncthreads();
        #pragma unroll
        for (int k = 0; k < 16; k++) {
            float4 av = *(const float4*)&As[k][ty << 2];
            float4 bv = *(const float4*)&Bs[k][tx << 2];
            float a[4] = {av.x, av.y, av.z, av.w};
            float b[4] = {bv.x, bv.y, bv.z, bv.w};
            #pragma unroll
            for (int i = 0; i < 4; i++)
                #pragma unroll
                for (int j = 0; j < 4; j++) acc[i][j] += a[i] * b[j];
        }
    }
    #pragma unroll
    for (int i = 0; i < 4; i++) {
        int m = blockIdx.y * 64 + (ty << 2) + i;
        #pragma unroll
        for (int j = 0; j < 4; j++)
            C[(size_t)m * N + blockIdx.x * 64 + (tx << 2) + j] = acc[i][j];
    }
}

// -------------------- Flash attention: 64q x 64k tiles, dh=64, online softmax --------
// grid (16 qtiles, 8 heads, 16 batch), 256 threads. Layouts merged-head [tok, 512].
__global__ __launch_bounds__(256) void attn_kernel(
    float* __restrict__ O, const float* __restrict__ Q,
    const float* __restrict__ K, const float* __restrict__ V)
{
    __shared__ float Qs[64][64];   // Qs[d][i]
    __shared__ float KP[64][64];   // Kst[d][j], then Pst[j][i]
    __shared__ float Vs[64][64];   // Vs[j][d]
    const int b = blockIdx.z, h = blockIdx.y;
    const int q0 = blockIdx.x * 64;
    const size_t base = (size_t)b * SEQL * D + h * 64;
    const int tid = threadIdx.x, tx = tid & 15, ty = tid >> 4;
    const int li = tid >> 2;              // row 0..63
    const int lc0 = (tid & 3) << 4;       // col base 0,16,32,48

    #pragma unroll
    for (int r = 0; r < 4; r++) {
        int ld = lc0 + (r << 2);
        float4 q4 = *(const float4*)(Q + base + (size_t)(q0 + li) * D + ld);
        Qs[ld + 0][li] = q4.x; Qs[ld + 1][li] = q4.y; Qs[ld + 2][li] = q4.z; Qs[ld + 3][li] = q4.w;
    }
    float o[4][4] = {};
    float mrow[4] = {-1e30f, -1e30f, -1e30f, -1e30f};
    float lrow[4] = {};

    for (int k0 = 0; k0 < SEQL; k0 += 64) {
        float4 k4[4], v4[4];
        #pragma unroll
        for (int r = 0; r < 4; r++) {
            int ld = lc0 + (r << 2);
            k4[r] = *(const float4*)(K + base + (size_t)(k0 + li) * D + ld);
            v4[r] = *(const float4*)(V + base + (size_t)(k0 + li) * D + ld);
        }
        __syncthreads();                       // prior P@V done reading KP/Vs
        #pragma unroll
        for (int r = 0; r < 4; r++) {
            int ld = lc0 + (r << 2);
            KP[ld + 0][li] = k4[r].x; KP[ld + 1][li] = k4[r].y;
            KP[ld + 2][li] = k4[r].z; KP[ld + 3][li] = k4[r].w;
            *(float4*)&Vs[li][ld] = v4[r];
        }
        __syncthreads();
        float s[4][4] = {};
        #pragma unroll
        for (int d = 0; d < 64; d++) {
            float4 qa = *(const float4*)&Qs[d][ty << 2];
            float4 kb = *(const float4*)&KP[d][tx << 2];
            float a[4] = {qa.x, qa.y, qa.z, qa.w};
            float c[4] = {kb.x, kb.y, kb.z, kb.w};
            #pragma unroll
            for (int i = 0; i < 4; i++)
                #pragma unroll
                for (int j = 0; j < 4; j++) s[i][j] += a[i] * c[j];
        }
        #pragma unroll
        for (int i = 0; i < 4; i++) {
            float m = -1e30f;
            #pragma unroll
            for (int j = 0; j < 4; j++) { s[i][j] *= ATT_SCALE; m = fmaxf(m, s[i][j]); }
            #pragma unroll
            for (int off = 8; off; off >>= 1) m = fmaxf(m, __shfl_xor_sync(0xffffffffu, m, off));
            float mn = fmaxf(mrow[i], m);
            float alpha = __expf(mrow[i] - mn);
            mrow[i] = mn;
            float rs = 0.f;
            #pragma unroll
            for (int j = 0; j < 4; j++) { s[i][j] = __expf(s[i][j] - mn); rs += s[i][j]; }
            #pragma unroll
            for (int off = 8; off; off >>= 1) rs += __shfl_xor_sync(0xffffffffu, rs, off);
            lrow[i] = lrow[i] * alpha + rs;
            #pragma unroll
            for (int j = 0; j < 4; j++) o[i][j] *= alpha;
        }
        __syncthreads();                       // done reading KP as Kst
        #pragma unroll
        for (int i = 0; i < 4; i++)
            #pragma unroll
            for (int j = 0; j < 4; j++) KP[(tx << 2) + j][(ty << 2) + i] = s[i][j];
        __syncthreads();
        #pragma unroll
        for (int j = 0; j < 64; j++) {
            float4 pa = *(const float4*)&KP[j][ty << 2];
            float4 vb = *(const float4*)&Vs[j][tx << 2];
            float a[4] = {pa.x, pa.y, pa.z, pa.w};
            float c[4] = {vb.x, vb.y, vb.z, vb.w};
            #pragma unroll
            for (int i = 0; i < 4; i++)
                #pragma unroll
                for (int jj = 0; jj < 4; jj++) o[i][jj] += a[i] * c[jj];
        }
    }
    #pragma unroll
    for (int i = 0; i < 4; i++) {
        float inv = 1.0f / lrow[i];
        float4 ov = make_float4(o[i][0] * inv, o[i][1] * inv, o[i][2] * inv, o[i][3] * inv);
        *(float4*)(O + base + (size_t)(q0 + (ty << 2) + i) * D + (tx << 2)) = ov;
    }
}

// -------------------- conv along feature dim (3-tap, zero-pad) --------------------
__global__ __launch_bounds__(128) void conv_row(
    float* __restrict__ out, const float* __restrict__ in, const float* __restrict__ w)
{
    __shared__ float rb[D];
    const int row = blockIdx.x, t = threadIdx.x;
    float4 v = *(const float4*)(in + (size_t)row * D + t * 4);
    *(float4*)&rb[t * 4] = v;
    __syncthreads();
    const float w0 = w[0], w1 = w[1], w2 = w[2];
    #pragma unroll
    for (int i = 0; i < 4; i++) {
        int c = t * 4 + i;
        float xm = (c > 0) ? rb[c - 1] : 0.f;
        float xp = (c < D - 1) ? rb[c + 1] : 0.f;
        out[(size_t)row * D + c] = w0 * xm + w1 * rb[c] + w2 * xp;
    }
}

// -------------------- LN(a+b)*g+be; optional hn side-output (raw a of last token) ----
__global__ __launch_bounds__(128) void ln_kernel(
    float* __restrict__ out, const float* __restrict__ a, const float* __restrict__ b,
    const float* __restrict__ g, const float* __restrict__ be,
    float* __restrict__ hn_out, int do_hn)
{
    __shared__ float sh[8];
    const int row = blockIdx.x, t = threadIdx.x;
    float4 av = *(const float4*)(a + (size_t)row * D + t * 4);
    float4 bv = *(const float4*)(b + (size_t)row * D + t * 4);
    float v[4] = {av.x + bv.x, av.y + bv.y, av.z + bv.z, av.w + bv.w};
    float s = v[0] + v[1] + v[2] + v[3];
    float s2 = v[0] * v[0] + v[1] * v[1] + v[2] * v[2] + v[3] * v[3];
    #pragma unroll
    for (int off = 16; off; off >>= 1) {
        s += __shfl_xor_sync(0xffffffffu, s, off);
        s2 += __shfl_xor_sync(0xffffffffu, s2, off);
    }
    if ((t & 31) == 0) { sh[t >> 5] = s; sh[4 + (t >> 5)] = s2; }
    __syncthreads();
    s = sh[0] + sh[1] + sh[2] + sh[3];
    s2 = sh[4] + sh[5] + sh[6] + sh[7];
    const float mean = s * (1.0f / D);
    const float rstd = rsqrtf(s2 * (1.0f / D) - mean * mean + 1e-5f);
    float4 gv = *(const float4*)(g + t * 4);
    float4 bev = *(const float4*)(be + t * 4);
    float4 ov = make_float4((v[0] - mean) * rstd * gv.x + bev.x,
                            (v[1] - mean) * rstd * gv.y + bev.y,
                            (v[2] - mean) * rstd * gv.z + bev.z,
                            (v[3] - mean) * rstd * gv.w + bev.w);
    *(float4*)(out + (size_t)row * D + t * 4) = ov;
    if (do_hn && (row & (SEQL - 1)) == SEQL - 1)
        *(float4*)(hn_out + (size_t)(row >> 10) * D + t * 4) = av;
}

// -------------------- fused LN1 + conv2: x1 = LN(a+b); x2c = conv(x1) ----------------
__global__ __launch_bounds__(128) void ln_conv_kernel(
    float* __restrict__ x1, float* __restrict__ x2c,
    const float* __restrict__ a, const float* __restrict__ b,
    const float* __restrict__ g, const float* __restrict__ be,
    const float* __restrict__ w)
{
    __shared__ float sh[8];
    __shared__ float rb[D];
    const int row = blockIdx.x, t = threadIdx.x;
    float4 av = *(const float4*)(a + (size_t)row * D + t * 4);
    float4 bv = *(const float4*)(b + (size_t)row * D + t * 4);
    float v[4] = {av.x + bv.x, av.y + bv.y, av.z + bv.z, av.w + bv.w};
    float s = v[0] + v[1] + v[2] + v[3];
    float s2 = v[0] * v[0] + v[1] * v[1] + v[2] * v[2] + v[3] * v[3];
    #pragma unroll
    for (int off = 16; off; off >>= 1) {
        s += __shfl_xor_sync(0xffffffffu, s, off);
        s2 += __shfl_xor_sync(0xffffffffu, s2, off);
    }
    if ((t & 31) == 0) { sh[t >> 5] = s; sh[4 + (t >> 5)] = s2; }
    __syncthreads();
    s = sh[0] + sh[1] + sh[2] + sh[3];
    s2 = sh[4] + sh[5] + sh[6] + sh[7];
    const float mean = s * (1.0f / D);
    const float rstd = rsqrtf(s2 * (1.0f / D) - mean * mean + 1e-5f);
    float4 gv = *(const float4*)(g + t * 4);
    float4 bev = *(const float4*)(be + t * 4);
    float y[4];
    y[0] = (v[0] - mean) * rstd * gv.x + bev.x;
    y[1] = (v[1] - mean) * rstd * gv.y + bev.y;
    y[2] = (v[2] - mean) * rstd * gv.z + bev.z;
    y[3] = (v[3] - mean) * rstd * gv.w + bev.w;
    *(float4*)&rb[t * 4] = make_float4(y[0], y[1], y[2], y[3]);
    *(float4*)(x1 + (size_t)row * D + t * 4) = make_float4(y[0], y[1], y[2], y[3]);
    __syncthreads();
    const float w0 = w[0], w1 = w[1], w2 = w[2];
    #pragma unroll
    for (int i = 0; i < 4; i++) {
        int c = t * 4 + i;
        float xm = (c > 0) ? rb[c - 1] : 0.f;
        float xp = (c < D - 1) ? rb[c + 1] : 0.f;
        x2c[(size_t)row * D + c] = w0 * xm + w1 * rb[c] + w2 * xp;
    }
}

// -------------------- launch --------------------
extern "C" void kernel_launch(void* const* d_in, const int* in_sizes, int n_in,
                              void* d_out, int out_size)
{
    const float* input   = (const float*)d_in[0];
    const float* wq_c    = (const float*)d_in[3];
    const float* fc_c    = (const float*)d_in[5];
    const float* wq_g    = (const float*)d_in[6];
    const float* wk_g    = (const float*)d_in[7];
    const float* fc_g    = (const float*)d_in[8];
    const float* wq_x    = (const float*)d_in[9];
    const float* fc_x    = (const float*)d_in[11];
    const float* conv1_w = (const float*)d_in[12];
    const float* conv2_w = (const float*)d_in[13];
    const float* ln1_g = (const float*)d_in[14];
    const float* ln1_b = (const float*)d_in[15];
    const float* ln2_g = (const float*)d_in[16];
    const float* ln2_b = (const float*)d_in[17];
    const float* ln3_g = (const float*)d_in[18];
    const float* ln3_b = (const float*)d_in[19];
    const float* ln4_g = (const float*)d_in[20];
    const float* ln4_b = (const float*)d_in[21];
    const float* mlp_w1 = (const float*)d_in[22];
    const float* mlp_b1 = (const float*)d_in[23];
    const float* mlp_w2 = (const float*)d_in[24];
    const float* mlp_b2 = (const float*)d_in[25];

    float *M1, *M3, *Kg, *Vg, *B0, *B1, *B2, *B3, *B4, *hid;
    cudaGetSymbolAddress((void**)&M1, d_M1);
    cudaGetSymbolAddress((void**)&M3, d_M3);
    cudaGetSymbolAddress((void**)&Kg, d_Kg);
    cudaGetSymbolAddress((void**)&Vg, d_Vg);
    cudaGetSymbolAddress((void**)&B0, d_B0);
    cudaGetSymbolAddress((void**)&B1, d_B1);
    cudaGetSymbolAddress((void**)&B2, d_B2);
    cudaGetSymbolAddress((void**)&B3, d_B3);
    cudaGetSymbolAddress((void**)&B4, d_B4);
    cudaGetSymbolAddress((void**)&hid, d_hid);

    float* outp = (float*)d_out;
    const size_t out_main = (size_t)N_TOK * D;
    float* hnp = outp + out_main;
    int do_hn = (out_size >= (int)(out_main + BSZ * D)) ? 1 : 0;
    if (!do_hn) hnp = outp;  // dummy, never written

    const dim3 blk(256);
    const dim3 g512(D / 64, N_TOK / 64);       // (8, 256)
    const dim3 g2048(DFF / 64, N_TOK / 64);    // (32, 256)
    const dim3 gW(D / 64, D / 64);             // (8, 8)

    // weight precomputation: M1 = fc_c @ wq_c, M3 = fc_x @ wq_x
    gemm_nn<<<gW, blk>>>(M1, fc_c, wq_c, D, D, D);
    gemm_nn<<<gW, blk>>>(M3, fc_x, wq_x, D, D, D);

    // gate K/V projections over full input
    gemm_tn<<<g512, blk>>>(Kg, input, wk_g, N_TOK, D, D, nullptr, 0);
    gemm_tn<<<g512, blk>>>(Vg, input, wq_g, N_TOK, D, D, nullptr, 0);

    // xc = conv1(input); u = xc @ M1^T; x1 = LN1(u + input); x2c = conv2(x1)
    conv_row<<<N_TOK, 128>>>(B0, input, conv1_w);
    gemm_tn<<<g512, blk>>>(B1, B0, M1, N_TOK, D, D, nullptr, 0);
    ln_conv_kernel<<<N_TOK, 128>>>(B2, B3, B1, input, ln1_g, ln1_b, conv2_w);

    // Q = x2c @ wq_g^T; att = MHA(Q, Kg, Vg); g = att @ fc_g^T; x2 = LN2(g + x1)
    gemm_tn<<<g512, blk>>>(B4, B3, wq_g, N_TOK, D, D, nullptr, 0);
    attn_kernel<<<dim3(SEQL / 64, 8, BSZ), blk>>>(B1, B4, Kg, Vg);
    gemm_tn<<<g512, blk>>>(B0, B1, fc_g, N_TOK, D, D, nullptr, 0);
    ln_kernel<<<N_TOK, 128>>>(B3, B0, B2, ln2_g, ln2_b, hnp, 0);

    // h = x2 @ M3^T; x3 = LN3(h + x2); hn = h of last token per batch
    gemm_tn<<<g512, blk>>>(B2, B3, M3, N_TOK, D, D, nullptr, 0);
    ln_kernel<<<N_TOK, 128>>>(B4, B2, B3, ln3_g, ln3_b, hnp, do_hn);

    // MLP: hid = gelu(x3 @ w1^T + b1); y = hid @ w2^T + b2; out = LN4(y + x3)
    gemm_tn<<<g2048, blk>>>(hid, B4, mlp_w1, N_TOK, DFF, D, mlp_b1, 1);
    gemm_tn<<<g512, blk>>>(B1, hid, mlp_w2, N_TOK, D, DFF, mlp_b2, 0);
    ln_kernel<<<N_TOK, 128>>>(outp, B1, B4, ln4_g, ln4_b, hnp, 0);
}

// round 4
// speedup vs baseline: 2.0065x; 2.0065x over previous
#include <cuda_runtime.h>
#include <cuda_bf16.h>
#include <math.h>
#include <stdint.h>

#define N_TOK 16384
#define D 512
#define SEQL 1024
#define BSZ 16
#define DFF 2048
#define ATT_SCALE 0.125f

// -------------------- scratch (__device__ globals; no allocation) --------------------
__device__ float d_M1[D * D];
__device__ float d_M3[D * D];
__device__ float d_Kg[(size_t)N_TOK * D];
__device__ float d_Vg[(size_t)N_TOK * D];
__device__ float d_B0[(size_t)N_TOK * D];
__device__ float d_B1[(size_t)N_TOK * D];
__device__ float d_B2[(size_t)N_TOK * D];
__device__ float d_B3[(size_t)N_TOK * D];
__device__ float d_B4[(size_t)N_TOK * D];
__device__ float d_hid[(size_t)N_TOK * DFF];

// ==================== helpers ====================
__device__ __forceinline__ uint32_t smem_u32(const void* p) {
    uint32_t a;
    asm("{ .reg .u64 t; cvta.to.shared.u64 t, %1; cvt.u32.u64 %0, t; }" : "=r"(a) : "l"(p));
    return a;
}
__device__ __forceinline__ void ldsm4(uint32_t addr, uint32_t& r0, uint32_t& r1, uint32_t& r2, uint32_t& r3) {
    asm volatile("ldmatrix.sync.aligned.m8n8.x4.shared.b16 {%0,%1,%2,%3}, [%4];"
                 : "=r"(r0), "=r"(r1), "=r"(r2), "=r"(r3) : "r"(addr));
}
__device__ __forceinline__ void mma_bf16(float c[4], const uint32_t a[4], uint32_t b0, uint32_t b1) {
    asm volatile(
        "mma.sync.aligned.m16n8k16.row.col.f32.bf16.bf16.f32 "
        "{%0,%1,%2,%3}, {%4,%5,%6,%7}, {%8,%9}, {%0,%1,%2,%3};"
        : "+f"(c[0]), "+f"(c[1]), "+f"(c[2]), "+f"(c[3])
        : "r"(a[0]), "r"(a[1]), "r"(a[2]), "r"(a[3]), "r"(b0), "r"(b1));
}
// split fp32 x4 into bf16 hi/lo pairs
__device__ __forceinline__ void split2(float4 v, uint2& hi, uint2& lo) {
    __nv_bfloat162 h0 = __float22bfloat162_rn(make_float2(v.x, v.y));
    __nv_bfloat162 h1 = __float22bfloat162_rn(make_float2(v.z, v.w));
    float2 f0 = __bfloat1622float2(h0), f1 = __bfloat1622float2(h1);
    __nv_bfloat162 l0 = __float22bfloat162_rn(make_float2(v.x - f0.x, v.y - f0.y));
    __nv_bfloat162 l1 = __float22bfloat162_rn(make_float2(v.z - f1.x, v.w - f1.y));
    hi = make_uint2(*(uint32_t*)&h0, *(uint32_t*)&h1);
    lo = make_uint2(*(uint32_t*)&l0, *(uint32_t*)&l1);
}

// ==================== split-bf16 mma.sync GEMM ====================
// C[M x Nt](fp32) = act(A[M x K] @ B[Nt x K]^T + bias). Tiles 128x128xBK64.
// 256 threads = 8 warps (4 x 2); warp tile 32x64 via m16n8k16.
#define KP 72                         // padded bf16 row stride (144 B)
#define T_AH 0
#define T_AL 18432
#define T_BH 36864
#define T_BL 55296
#define TCG_SMEM 73728

__global__ __launch_bounds__(256, 1) void mma_gemm(
    float* __restrict__ C, const float* __restrict__ A, const float* __restrict__ B,
    int M, int Nt, int K, const float* __restrict__ bias, int act)
{
    extern __shared__ char smem[];
    const uint32_t sb = smem_u32(smem);
    const int tid = threadIdx.x, wid = tid >> 5, lane = tid & 31;
    const int m0 = blockIdx.y * 128, n0 = blockIdx.x * 128;
    const int wm = (wid & 3) << 5;    // warp row offset within tile
    const int wn = (wid >> 2) << 6;   // warp col offset within tile

    // ldmatrix lane addressing
    const int quad = lane >> 3, r = lane & 7;
    const int arow = ((quad & 1) << 3) + r, ak = (quad >> 1) << 3;
    const int brow = ((quad >> 1) << 3) + r, bk = (quad & 1) << 3;

    // global-load assignment: 8 rows/thread, fixed 16-float slot
    const int ldr = tid >> 4;
    const int lds = (tid & 15) << 2;

    float acc[2][8][4];
    #pragma unroll
    for (int i = 0; i < 2; i++)
        #pragma unroll
        for (int j = 0; j < 8; j++)
            #pragma unroll
            for (int q = 0; q < 4; q++) acc[i][j][q] = 0.f;

    const int nit = K >> 6;
    float4 av[8], bv[8];
    #pragma unroll
    for (int j = 0; j < 8; j++) {
        int row = ldr + (j << 4);
        av[j] = *(const float4*)(A + (size_t)(m0 + row) * K + lds);
        bv[j] = *(const float4*)(B + (size_t)(n0 + row) * K + lds);
    }

    for (int it = 0; it < nit; it++) {
        #pragma unroll
        for (int j = 0; j < 8; j++) {
            int row = ldr + (j << 4);
            uint32_t off = row * (KP * 2) + (tid & 15) * 8;
            uint2 h, l;
            split2(av[j], h, l);
            *(uint2*)(smem + T_AH + off) = h;
            *(uint2*)(smem + T_AL + off) = l;
            split2(bv[j], h, l);
            *(uint2*)(smem + T_BH + off) = h;
            *(uint2*)(smem + T_BL + off) = l;
        }
        __syncthreads();
        if (it + 1 < nit) {
            const int k0 = (it + 1) << 6;
            #pragma unroll
            for (int j = 0; j < 8; j++) {
                int row = ldr + (j << 4);
                av[j] = *(const float4*)(A + (size_t)(m0 + row) * K + k0 + lds);
                bv[j] = *(const float4*)(B + (size_t)(n0 + row) * K + k0 + lds);
            }
        }
        #pragma unroll
        for (int kc = 0; kc < 4; kc++) {
            uint32_t ah[2][4], al[2][4];
            #pragma unroll
            for (int i = 0; i < 2; i++) {
                uint32_t ao = sb + ((wm + (i << 4) + arow) * KP + (kc << 4) + ak) * 2;
                ldsm4(ao + T_AH, ah[i][0], ah[i][1], ah[i][2], ah[i][3]);
                ldsm4(ao + T_AL, al[i][0], al[i][1], al[i][2], al[i][3]);
            }
            #pragma unroll
            for (int jj = 0; jj < 4; jj++) {
                uint32_t bo = sb + ((wn + (jj << 4) + brow) * KP + (kc << 4) + bk) * 2;
                uint32_t bh0, bh1, bh2, bh3, bl0, bl1, bl2, bl3;
                ldsm4(bo + T_BH, bh0, bh1, bh2, bh3);
                ldsm4(bo + T_BL, bl0, bl1, bl2, bl3);
                #pragma unroll
                for (int i = 0; i < 2; i++) {
                    mma_bf16(acc[i][2 * jj],     ah[i], bh0, bh1);
                    mma_bf16(acc[i][2 * jj],     ah[i], bl0, bl1);
                    mma_bf16(acc[i][2 * jj],     al[i], bh0, bh1);
                    mma_bf16(acc[i][2 * jj + 1], ah[i], bh2, bh3);
                    mma_bf16(acc[i][2 * jj + 1], ah[i], bl2, bl3);
                    mma_bf16(acc[i][2 * jj + 1], al[i], bh2, bh3);
                }
            }
        }
        __syncthreads();
    }

    // epilogue
    const int g = lane >> 2, tg = (lane & 3) << 1;
    #pragma unroll
    for (int i = 0; i < 2; i++) {
        const int row0 = m0 + wm + (i << 4) + g;
        #pragma unroll
        for (int j = 0; j < 8; j++) {
            const int col = n0 + wn + (j << 3) + tg;
            float b0 = 0.f, b1 = 0.f;
            if (bias) { b0 = bias[col]; b1 = bias[col + 1]; }
            float v0 = acc[i][j][0] + b0, v1 = acc[i][j][1] + b1;
            float v2 = acc[i][j][2] + b0, v3 = acc[i][j][3] + b1;
            if (act) {
                v0 = 0.5f * v0 * (1.0f + erff(v0 * 0.70710678118654752f));
                v1 = 0.5f * v1 * (1.0f + erff(v1 * 0.70710678118654752f));
                v2 = 0.5f * v2 * (1.0f + erff(v2 * 0.70710678118654752f));
                v3 = 0.5f * v3 * (1.0f + erff(v3 * 0.70710678118654752f));
            }
            *(float2*)(C + (size_t)row0 * Nt + col) = make_float2(v0, v1);
            *(float2*)(C + (size_t)(row0 + 8) * Nt + col) = make_float2(v2, v3);
        }
    }
}

// -------------------- GEMM NN (fp32, tiny: 512^3 weight folding) --------------------
__global__ __launch_bounds__(256) void gemm_nn(
    float* __restrict__ C, const float* __restrict__ A, const float* __restrict__ B,
    int M, int N, int K)
{
    __shared__ float As[16][64];
    __shared__ float Bs[16][64];
    const int tid = threadIdx.x;
    const int tx = tid & 15, ty = tid >> 4;
    const int lr = tid >> 2, lc = (tid & 3) << 2;
    const int bkr = tid >> 4, bnc = (tid & 15) << 2;
    const float* Ab = A + (size_t)blockIdx.y * 64 * K;
    float acc[4][4] = {};
    for (int k0 = 0; k0 < K; k0 += 16) {
        float4 a4 = *(const float4*)(Ab + (size_t)lr * K + k0 + lc);
        float4 b4 = *(const float4*)(B + (size_t)(k0 + bkr) * N + blockIdx.x * 64 + bnc);
        __syncthreads();
        As[lc + 0][lr] = a4.x; As[lc + 1][lr] = a4.y; As[lc + 2][lr] = a4.z; As[lc + 3][lr] = a4.w;
        *(float4*)&Bs[bkr][bnc] = b4;
        __syncthreads();
        #pragma unroll
        for (int k = 0; k < 16; k++) {
            float4 av = *(const float4*)&As[k][ty << 2];
            float4 bv = *(const float4*)&Bs[k][tx << 2];
            float a[4] = {av.x, av.y, av.z, av.w};
            float b[4] = {bv.x, bv.y, bv.z, bv.w};
            #pragma unroll
            for (int i = 0; i < 4; i++)
                #pragma unroll
                for (int j = 0; j < 4; j++) acc[i][j] += a[i] * b[j];
        }
    }
    #pragma unroll
    for (int i = 0; i < 4; i++) {
        int m = blockIdx.y * 64 + (ty << 2) + i;
        #pragma unroll
        for (int j = 0; j < 4; j++)
            C[(size_t)m * N + blockIdx.x * 64 + (tx << 2) + j] = acc[i][j];
    }
}

// -------------------- Flash attention (fp32, 64x64 tiles) --------------------
__global__ __launch_bounds__(256) void attn_kernel(
    float* __restrict__ O, const float* __restrict__ Q,
    const float* __restrict__ K, const float* __restrict__ V)
{
    __shared__ float Qs[64][64];
    __shared__ float KP_s[64][64];
    __shared__ float Vs[64][64];
    const int b = blockIdx.z, h = blockIdx.y;
    const int q0 = blockIdx.x * 64;
    const size_t base = (size_t)b * SEQL * D + h * 64;
    const int tid = threadIdx.x, tx = tid & 15, ty = tid >> 4;
    const int li = tid >> 2;
    const int lc0 = (tid & 3) << 4;

    #pragma unroll
    for (int r = 0; r < 4; r++) {
        int ld = lc0 + (r << 2);
        float4 q4 = *(const float4*)(Q + base + (size_t)(q0 + li) * D + ld);
        Qs[ld + 0][li] = q4.x; Qs[ld + 1][li] = q4.y; Qs[ld + 2][li] = q4.z; Qs[ld + 3][li] = q4.w;
    }
    float o[4][4] = {};
    float mrow[4] = {-1e30f, -1e30f, -1e30f, -1e30f};
    float lrow[4] = {};

    for (int k0 = 0; k0 < SEQL; k0 += 64) {
        float4 k4[4], v4[4];
        #pragma unroll
        for (int r = 0; r < 4; r++) {
            int ld = lc0 + (r << 2);
            k4[r] = *(const float4*)(K + base + (size_t)(k0 + li) * D + ld);
            v4[r] = *(const float4*)(V + base + (size_t)(k0 + li) * D + ld);
        }
        __syncthreads();
        #pragma unroll
        for (int r = 0; r < 4; r++) {
            int ld = lc0 + (r << 2);
            KP_s[ld + 0][li] = k4[r].x; KP_s[ld + 1][li] = k4[r].y;
            KP_s[ld + 2][li] = k4[r].z; KP_s[ld + 3][li] = k4[r].w;
            *(float4*)&Vs[li][ld] = v4[r];
        }
        __syncthreads();
        float s[4][4] = {};
        #pragma unroll
        for (int d = 0; d < 64; d++) {
            float4 qa = *(const float4*)&Qs[d][ty << 2];
            float4 kb = *(const float4*)&KP_s[d][tx << 2];
            float a[4] = {qa.x, qa.y, qa.z, qa.w};
            float c[4] = {kb.x, kb.y, kb.z, kb.w};
            #pragma unroll
            for (int i = 0; i < 4; i++)
                #pragma unroll
                for (int j = 0; j < 4; j++) s[i][j] += a[i] * c[j];
        }
        #pragma unroll
        for (int i = 0; i < 4; i++) {
            float m = -1e30f;
            #pragma unroll
            for (int j = 0; j < 4; j++) { s[i][j] *= ATT_SCALE; m = fmaxf(m, s[i][j]); }
            #pragma unroll
            for (int off = 8; off; off >>= 1) m = fmaxf(m, __shfl_xor_sync(0xffffffffu, m, off));
            float mn = fmaxf(mrow[i], m);
            float alpha = __expf(mrow[i] - mn);
            mrow[i] = mn;
            float rs = 0.f;
            #pragma unroll
            for (int j = 0; j < 4; j++) { s[i][j] = __expf(s[i][j] - mn); rs += s[i][j]; }
            #pragma unroll
            for (int off = 8; off; off >>= 1) rs += __shfl_xor_sync(0xffffffffu, rs, off);
            lrow[i] = lrow[i] * alpha + rs;
            #pragma unroll
            for (int j = 0; j < 4; j++) o[i][j] *= alpha;
        }
        __syncthreads();
        #pragma unroll
        for (int i = 0; i < 4; i++)
            #pragma unroll
            for (int j = 0; j < 4; j++) KP_s[(tx << 2) + j][(ty << 2) + i] = s[i][j];
        __syncthreads();
        #pragma unroll
        for (int j = 0; j < 64; j++) {
            float4 pa = *(const float4*)&KP_s[j][ty << 2];
            float4 vb = *(const float4*)&Vs[j][tx << 2];
            float a[4] = {pa.x, pa.y, pa.z, pa.w};
            float c[4] = {vb.x, vb.y, vb.z, vb.w};
            #pragma unroll
            for (int i = 0; i < 4; i++)
                #pragma unroll
                for (int jj = 0; jj < 4; jj++) o[i][jj] += a[i] * c[jj];
        }
    }
    #pragma unroll
    for (int i = 0; i < 4; i++) {
        float inv = 1.0f / lrow[i];
        float4 ov = make_float4(o[i][0] * inv, o[i][1] * inv, o[i][2] * inv, o[i][3] * inv);
        *(float4*)(O + base + (size_t)(q0 + (ty << 2) + i) * D + (tx << 2)) = ov;
    }
}

// -------------------- conv along feature dim (3-tap, zero-pad) --------------------
__global__ __launch_bounds__(128) void conv_row(
    float* __restrict__ out, const float* __restrict__ in, const float* __restrict__ w)
{
    __shared__ float rb[D];
    const int row = blockIdx.x, t = threadIdx.x;
    float4 v = *(const float4*)(in + (size_t)row * D + t * 4);
    *(float4*)&rb[t * 4] = v;
    __syncthreads();
    const float w0 = w[0], w1 = w[1], w2 = w[2];
    #pragma unroll
    for (int i = 0; i < 4; i++) {
        int c = t * 4 + i;
        float xm = (c > 0) ? rb[c - 1] : 0.f;
        float xp = (c < D - 1) ? rb[c + 1] : 0.f;
        out[(size_t)row * D + c] = w0 * xm + w1 * rb[c] + w2 * xp;
    }
}

// -------------------- LN(a+b)*g+be; optional hn side-output --------------------
__global__ __launch_bounds__(128) void ln_kernel(
    float* __restrict__ out, const float* __restrict__ a, const float* __restrict__ b,
    const float* __restrict__ g, const float* __restrict__ be,
    float* __restrict__ hn_out, int do_hn)
{
    __shared__ float sh[8];
    const int row = blockIdx.x, t = threadIdx.x;
    float4 av = *(const float4*)(a + (size_t)row * D + t * 4);
    float4 bv = *(const float4*)(b + (size_t)row * D + t * 4);
    float v[4] = {av.x + bv.x, av.y + bv.y, av.z + bv.z, av.w + bv.w};
    float s = v[0] + v[1] + v[2] + v[3];
    float s2 = v[0] * v[0] + v[1] * v[1] + v[2] * v[2] + v[3] * v[3];
    #pragma unroll
    for (int off = 16; off; off >>= 1) {
        s += __shfl_xor_sync(0xffffffffu, s, off);
        s2 += __shfl_xor_sync(0xffffffffu, s2, off);
    }
    if ((t & 31) == 0) { sh[t >> 5] = s; sh[4 + (t >> 5)] = s2; }
    __syncthreads();
    s = sh[0] + sh[1] + sh[2] + sh[3];
    s2 = sh[4] + sh[5] + sh[6] + sh[7];
    const float mean = s * (1.0f / D);
    const float rstd = rsqrtf(s2 * (1.0f / D) - mean * mean + 1e-5f);
    float4 gv = *(const float4*)(g + t * 4);
    float4 bev = *(const float4*)(be + t * 4);
    float4 ov = make_float4((v[0] - mean) * rstd * gv.x + bev.x,
                            (v[1] - mean) * rstd * gv.y + bev.y,
                            (v[2] - mean) * rstd * gv.z + bev.z,
                            (v[3] - mean) * rstd * gv.w + bev.w);
    *(float4*)(out + (size_t)row * D + t * 4) = ov;
    if (do_hn && (row & (SEQL - 1)) == SEQL - 1)
        *(float4*)(hn_out + (size_t)(row >> 10) * D + t * 4) = av;
}

// -------------------- fused LN1 + conv2 --------------------
__global__ __launch_bounds__(128) void ln_conv_kernel(
    float* __restrict__ x1, float* __restrict__ x2c,
    const float* __restrict__ a, const float* __restrict__ b,
    const float* __restrict__ g, const float* __restrict__ be,
    const float* __restrict__ w)
{
    __shared__ float sh[8];
    __shared__ float rb[D];
    const int row = blockIdx.x, t = threadIdx.x;
    float4 av = *(const float4*)(a + (size_t)row * D + t * 4);
    float4 bv = *(const float4*)(b + (size_t)row * D + t * 4);
    float v[4] = {av.x + bv.x, av.y + bv.y, av.z + bv.z, av.w + bv.w};
    float s = v[0] + v[1] + v[2] + v[3];
    float s2 = v[0] * v[0] + v[1] * v[1] + v[2] * v[2] + v[3] * v[3];
    #pragma unroll
    for (int off = 16; off; off >>= 1) {
        s += __shfl_xor_sync(0xffffffffu, s, off);
        s2 += __shfl_xor_sync(0xffffffffu, s2, off);
    }
    if ((t & 31) == 0) { sh[t >> 5] = s; sh[4 + (t >> 5)] = s2; }
    __syncthreads();
    s = sh[0] + sh[1] + sh[2] + sh[3];
    s2 = sh[4] + sh[5] + sh[6] + sh[7];
    const float mean = s * (1.0f / D);
    const float rstd = rsqrtf(s2 * (1.0f / D) - mean * mean + 1e-5f);
    float4 gv = *(const float4*)(g + t * 4);
    float4 bev = *(const float4*)(be + t * 4);
    float y[4];
    y[0] = (v[0] - mean) * rstd * gv.x + bev.x;
    y[1] = (v[1] - mean) * rstd * gv.y + bev.y;
    y[2] = (v[2] - mean) * rstd * gv.z + bev.z;
    y[3] = (v[3] - mean) * rstd * gv.w + bev.w;
    *(float4*)&rb[t * 4] = make_float4(y[0], y[1], y[2], y[3]);
    *(float4*)(x1 + (size_t)row * D + t * 4) = make_float4(y[0], y[1], y[2], y[3]);
    __syncthreads();
    const float w0 = w[0], w1 = w[1], w2 = w[2];
    #pragma unroll
    for (int i = 0; i < 4; i++) {
        int c = t * 4 + i;
        float xm = (c > 0) ? rb[c - 1] : 0.f;
        float xp = (c < D - 1) ? rb[c + 1] : 0.f;
        x2c[(size_t)row * D + c] = w0 * xm + w1 * rb[c] + w2 * xp;
    }
}

// -------------------- launch --------------------
extern "C" void kernel_launch(void* const* d_in, const int* in_sizes, int n_in,
                              void* d_out, int out_size)
{
    const float* input   = (const float*)d_in[0];
    const float* wq_c    = (const float*)d_in[3];
    const float* fc_c    = (const float*)d_in[5];
    const float* wq_g    = (const float*)d_in[6];
    const float* wk_g    = (const float*)d_in[7];
    const float* fc_g    = (const float*)d_in[8];
    const float* wq_x    = (const float*)d_in[9];
    const float* fc_x    = (const float*)d_in[11];
    const float* conv1_w = (const float*)d_in[12];
    const float* conv2_w = (const float*)d_in[13];
    const float* ln1_g = (const float*)d_in[14];
    const float* ln1_b = (const float*)d_in[15];
    const float* ln2_g = (const float*)d_in[16];
    const float* ln2_b = (const float*)d_in[17];
    const float* ln3_g = (const float*)d_in[18];
    const float* ln3_b = (const float*)d_in[19];
    const float* ln4_g = (const float*)d_in[20];
    const float* ln4_b = (const float*)d_in[21];
    const float* mlp_w1 = (const float*)d_in[22];
    const float* mlp_b1 = (const float*)d_in[23];
    const float* mlp_w2 = (const float*)d_in[24];
    const float* mlp_b2 = (const float*)d_in[25];

    float *M1, *M3, *Kg, *Vg, *B0, *B1, *B2, *B3, *B4, *hid;
    cudaGetSymbolAddress((void**)&M1, d_M1);
    cudaGetSymbolAddress((void**)&M3, d_M3);
    cudaGetSymbolAddress((void**)&Kg, d_Kg);
    cudaGetSymbolAddress((void**)&Vg, d_Vg);
    cudaGetSymbolAddress((void**)&B0, d_B0);
    cudaGetSymbolAddress((void**)&B1, d_B1);
    cudaGetSymbolAddress((void**)&B2, d_B2);
    cudaGetSymbolAddress((void**)&B3, d_B3);
    cudaGetSymbolAddress((void**)&B4, d_B4);
    cudaGetSymbolAddress((void**)&hid, d_hid);

    cudaFuncSetAttribute(mma_gemm, cudaFuncAttributeMaxDynamicSharedMemorySize, TCG_SMEM);

    float* outp = (float*)d_out;
    const size_t out_main = (size_t)N_TOK * D;
    float* hnp = outp + out_main;
    int do_hn = (out_size >= (int)(out_main + BSZ * D)) ? 1 : 0;
    if (!do_hn) hnp = outp;

    const dim3 blk(256);
    const dim3 tg512(D / 128, N_TOK / 128);     // (4, 128)
    const dim3 tg2048(DFF / 128, N_TOK / 128);  // (16, 128)
    const dim3 gW(D / 64, D / 64);

    // weight folding: M1 = fc_c @ wq_c, M3 = fc_x @ wq_x  (fp32, tiny)
    gemm_nn<<<gW, blk>>>(M1, fc_c, wq_c, D, D, D);
    gemm_nn<<<gW, blk>>>(M3, fc_x, wq_x, D, D, D);

    // gate K/V projections over full input
    mma_gemm<<<tg512, blk, TCG_SMEM>>>(Kg, input, wk_g, N_TOK, D, D, nullptr, 0);
    mma_gemm<<<tg512, blk, TCG_SMEM>>>(Vg, input, wq_g, N_TOK, D, D, nullptr, 0);

    // xc = conv1(input); u = xc @ M1^T; x1 = LN1(u + input); x2c = conv2(x1)
    conv_row<<<N_TOK, 128>>>(B0, input, conv1_w);
    mma_gemm<<<tg512, blk, TCG_SMEM>>>(B1, B0, M1, N_TOK, D, D, nullptr, 0);
    ln_conv_kernel<<<N_TOK, 128>>>(B2, B3, B1, input, ln1_g, ln1_b, conv2_w);

    // Q = x2c @ wq_g^T; att = MHA(Q, Kg, Vg); g = att @ fc_g^T; x2 = LN2(g + x1)
    mma_gemm<<<tg512, blk, TCG_SMEM>>>(B4, B3, wq_g, N_TOK, D, D, nullptr, 0);
    attn_kernel<<<dim3(SEQL / 64, 8, BSZ), blk>>>(B1, B4, Kg, Vg);
    mma_gemm<<<tg512, blk, TCG_SMEM>>>(B0, B1, fc_g, N_TOK, D, D, nullptr, 0);
    ln_kernel<<<N_TOK, 128>>>(B3, B0, B2, ln2_g, ln2_b, hnp, 0);

    // h = x2 @ M3^T; x3 = LN3(h + x2); hn = h of last token per batch
    mma_gemm<<<tg512, blk, TCG_SMEM>>>(B2, B3, M3, N_TOK, D, D, nullptr, 0);
    ln_kernel<<<N_TOK, 128>>>(B4, B2, B3, ln3_g, ln3_b, hnp, do_hn);

    // MLP: hid = gelu(x3 @ w1^T + b1); y = hid @ w2^T + b2; out = LN4(y + x3)
    mma_gemm<<<tg2048, blk, TCG_SMEM>>>(hid, B4, mlp_w1, N_TOK, DFF, D, mlp_b1, 1);
    mma_gemm<<<tg512, blk, TCG_SMEM>>>(B1, hid, mlp_w2, N_TOK, D, DFF, mlp_b2, 0);
    ln_kernel<<<N_TOK, 128>>>(outp, B1, B4, ln4_g, ln4_b, hnp, 0);
}

// round 6
// speedup vs baseline: 3.1686x; 1.5792x over previous
#include <cuda_runtime.h>
#include <cuda_bf16.h>
#include <math.h>
#include <stdint.h>

#define N_TOK 16384
#define D 512
#define SEQL 1024
#define BSZ 16
#define DFF 2048
#define ATT_SCALE 0.125f

// -------------------- scratch (__device__ globals; no allocation) --------------------
__device__ float d_M1[D * D];
__device__ float d_M3[D * D];
__device__ float d_Kg[(size_t)N_TOK * D];
__device__ float d_Vg[(size_t)N_TOK * D];
__device__ float d_B0[(size_t)N_TOK * D];
__device__ float d_B1[(size_t)N_TOK * D];
__device__ float d_B2[(size_t)N_TOK * D];
__device__ float d_B3[(size_t)N_TOK * D];
__device__ float d_B4[(size_t)N_TOK * D];
__device__ float d_hid[(size_t)N_TOK * DFF];

// ==================== helpers ====================
__device__ __forceinline__ uint32_t smem_u32(const void* p) {
    uint32_t a;
    asm("{ .reg .u64 t; cvta.to.shared.u64 t, %1; cvt.u32.u64 %0, t; }" : "=r"(a) : "l"(p));
    return a;
}
__device__ __forceinline__ void ldsm4(uint32_t addr, uint32_t& r0, uint32_t& r1, uint32_t& r2, uint32_t& r3) {
    asm volatile("ldmatrix.sync.aligned.m8n8.x4.shared.b16 {%0,%1,%2,%3}, [%4];"
                 : "=r"(r0), "=r"(r1), "=r"(r2), "=r"(r3) : "r"(addr));
}
__device__ __forceinline__ void mma_bf16(float c[4], const uint32_t a[4], uint32_t b0, uint32_t b1) {
    asm volatile(
        "mma.sync.aligned.m16n8k16.row.col.f32.bf16.bf16.f32 "
        "{%0,%1,%2,%3}, {%4,%5,%6,%7}, {%8,%9}, {%0,%1,%2,%3};"
        : "+f"(c[0]), "+f"(c[1]), "+f"(c[2]), "+f"(c[3])
        : "r"(a[0]), "r"(a[1]), "r"(a[2]), "r"(a[3]), "r"(b0), "r"(b1));
}
__device__ __forceinline__ void split2(float4 v, uint2& hi, uint2& lo) {
    __nv_bfloat162 h0 = __float22bfloat162_rn(make_float2(v.x, v.y));
    __nv_bfloat162 h1 = __float22bfloat162_rn(make_float2(v.z, v.w));
    float2 f0 = __bfloat1622float2(h0), f1 = __bfloat1622float2(h1);
    __nv_bfloat162 l0 = __float22bfloat162_rn(make_float2(v.x - f0.x, v.y - f0.y));
    __nv_bfloat162 l1 = __float22bfloat162_rn(make_float2(v.z - f1.x, v.w - f1.y));
    hi = make_uint2(*(uint32_t*)&h0, *(uint32_t*)&h1);
    lo = make_uint2(*(uint32_t*)&l0, *(uint32_t*)&l1);
}

// ==================== split-bf16 mma.sync GEMM (unchanged from R4) ====================
#define KP 72
#define T_AH 0
#define T_AL 18432
#define T_BH 36864
#define T_BL 55296
#define TCG_SMEM 73728

__global__ __launch_bounds__(256, 1) void mma_gemm(
    float* __restrict__ C, const float* __restrict__ A, const float* __restrict__ B,
    int M, int Nt, int K, const float* __restrict__ bias, int act)
{
    extern __shared__ char smem[];
    const uint32_t sb = smem_u32(smem);
    const int tid = threadIdx.x, wid = tid >> 5, lane = tid & 31;
    const int m0 = blockIdx.y * 128, n0 = blockIdx.x * 128;
    const int wm = (wid & 3) << 5;
    const int wn = (wid >> 2) << 6;
    const int quad = lane >> 3, r = lane & 7;
    const int arow = ((quad & 1) << 3) + r, ak = (quad >> 1) << 3;
    const int brow = ((quad >> 1) << 3) + r, bk = (quad & 1) << 3;
    const int ldr = tid >> 4;
    const int lds = (tid & 15) << 2;

    float acc[2][8][4];
    #pragma unroll
    for (int i = 0; i < 2; i++)
        #pragma unroll
        for (int j = 0; j < 8; j++)
            #pragma unroll
            for (int q = 0; q < 4; q++) acc[i][j][q] = 0.f;

    const int nit = K >> 6;
    float4 av[8], bv[8];
    #pragma unroll
    for (int j = 0; j < 8; j++) {
        int row = ldr + (j << 4);
        av[j] = *(const float4*)(A + (size_t)(m0 + row) * K + lds);
        bv[j] = *(const float4*)(B + (size_t)(n0 + row) * K + lds);
    }

    for (int it = 0; it < nit; it++) {
        #pragma unroll
        for (int j = 0; j < 8; j++) {
            int row = ldr + (j << 4);
            uint32_t off = row * (KP * 2) + (tid & 15) * 8;
            uint2 h, l;
            split2(av[j], h, l);
            *(uint2*)(smem + T_AH + off) = h;
            *(uint2*)(smem + T_AL + off) = l;
            split2(bv[j], h, l);
            *(uint2*)(smem + T_BH + off) = h;
            *(uint2*)(smem + T_BL + off) = l;
        }
        __syncthreads();
        if (it + 1 < nit) {
            const int k0 = (it + 1) << 6;
            #pragma unroll
            for (int j = 0; j < 8; j++) {
                int row = ldr + (j << 4);
                av[j] = *(const float4*)(A + (size_t)(m0 + row) * K + k0 + lds);
                bv[j] = *(const float4*)(B + (size_t)(n0 + row) * K + k0 + lds);
            }
        }
        #pragma unroll
        for (int kc = 0; kc < 4; kc++) {
            uint32_t ah[2][4], al[2][4];
            #pragma unroll
            for (int i = 0; i < 2; i++) {
                uint32_t ao = sb + ((wm + (i << 4) + arow) * KP + (kc << 4) + ak) * 2;
                ldsm4(ao + T_AH, ah[i][0], ah[i][1], ah[i][2], ah[i][3]);
                ldsm4(ao + T_AL, al[i][0], al[i][1], al[i][2], al[i][3]);
            }
            #pragma unroll
            for (int jj = 0; jj < 4; jj++) {
                uint32_t bo = sb + ((wn + (jj << 4) + brow) * KP + (kc << 4) + bk) * 2;
                uint32_t bh0, bh1, bh2, bh3, bl0, bl1, bl2, bl3;
                ldsm4(bo + T_BH, bh0, bh1, bh2, bh3);
                ldsm4(bo + T_BL, bl0, bl1, bl2, bl3);
                #pragma unroll
                for (int i = 0; i < 2; i++) {
                    mma_bf16(acc[i][2 * jj],     ah[i], bh0, bh1);
                    mma_bf16(acc[i][2 * jj],     ah[i], bl0, bl1);
                    mma_bf16(acc[i][2 * jj],     al[i], bh0, bh1);
                    mma_bf16(acc[i][2 * jj + 1], ah[i], bh2, bh3);
                    mma_bf16(acc[i][2 * jj + 1], ah[i], bl2, bl3);
                    mma_bf16(acc[i][2 * jj + 1], al[i], bh2, bh3);
                }
            }
        }
        __syncthreads();
    }

    const int g = lane >> 2, tg = (lane & 3) << 1;
    #pragma unroll
    for (int i = 0; i < 2; i++) {
        const int row0 = m0 + wm + (i << 4) + g;
        #pragma unroll
        for (int j = 0; j < 8; j++) {
            const int col = n0 + wn + (j << 3) + tg;
            float b0 = 0.f, b1 = 0.f;
            if (bias) { b0 = bias[col]; b1 = bias[col + 1]; }
            float v0 = acc[i][j][0] + b0, v1 = acc[i][j][1] + b1;
            float v2 = acc[i][j][2] + b0, v3 = acc[i][j][3] + b1;
            if (act) {
                v0 = 0.5f * v0 * (1.0f + erff(v0 * 0.70710678118654752f));
                v1 = 0.5f * v1 * (1.0f + erff(v1 * 0.70710678118654752f));
                v2 = 0.5f * v2 * (1.0f + erff(v2 * 0.70710678118654752f));
                v3 = 0.5f * v3 * (1.0f + erff(v3 * 0.70710678118654752f));
            }
            *(float2*)(C + (size_t)row0 * Nt + col) = make_float2(v0, v1);
            *(float2*)(C + (size_t)(row0 + 8) * Nt + col) = make_float2(v2, v3);
        }
    }
}

// -------------------- GEMM NN (fp32, tiny: weight folding) --------------------
__global__ __launch_bounds__(256) void gemm_nn(
    float* __restrict__ C, const float* __restrict__ A, const float* __restrict__ B,
    int M, int N, int K)
{
    __shared__ float As[16][64];
    __shared__ float Bs[16][64];
    const int tid = threadIdx.x;
    const int tx = tid & 15, ty = tid >> 4;
    const int lr = tid >> 2, lc = (tid & 3) << 2;
    const int bkr = tid >> 4, bnc = (tid & 15) << 2;
    const float* Ab = A + (size_t)blockIdx.y * 64 * K;
    float acc[4][4] = {};
    for (int k0 = 0; k0 < K; k0 += 16) {
        float4 a4 = *(const float4*)(Ab + (size_t)lr * K + k0 + lc);
        float4 b4 = *(const float4*)(B + (size_t)(k0 + bkr) * N + blockIdx.x * 64 + bnc);
        __syncthreads();
        As[lc + 0][lr] = a4.x; As[lc + 1][lr] = a4.y; As[lc + 2][lr] = a4.z; As[lc + 3][lr] = a4.w;
        *(float4*)&Bs[bkr][bnc] = b4;
        __syncthreads();
        #pragma unroll
        for (int k = 0; k < 16; k++) {
            float4 av = *(const float4*)&As[k][ty << 2];
            float4 bv = *(const float4*)&Bs[k][tx << 2];
            float a[4] = {av.x, av.y, av.z, av.w};
            float b[4] = {bv.x, bv.y, bv.z, bv.w};
            #pragma unroll
            for (int i = 0; i < 4; i++)
                #pragma unroll
                for (int j = 0; j < 4; j++) acc[i][j] += a[i] * b[j];
        }
    }
    #pragma unroll
    for (int i = 0; i < 4; i++) {
        int m = blockIdx.y * 64 + (ty << 2) + i;
        #pragma unroll
        for (int j = 0; j < 4; j++)
            C[(size_t)m * N + blockIdx.x * 64 + (tx << 2) + j] = acc[i][j];
    }
}

// ==================== tensor-core flash attention ====================
// Block: 128 q-rows x one (head, batch). 8 warps x 16 q-rows. K/V tiles of 64.
// QK: split-bf16 3-term. PV: plain bf16 (P from register repack of C frags).
#define AT_QH 0
#define AT_QL 18432
#define AT_KH 36864
#define AT_KL 46080
#define AT_VT 55296
#define AT_SMEM 64512

__global__ __launch_bounds__(256, 1) void attn_mma(
    float* __restrict__ O, const float* __restrict__ Q,
    const float* __restrict__ K, const float* __restrict__ V)
{
    extern __shared__ char smem[];
    const uint32_t sb = smem_u32(smem);
    const int tid = threadIdx.x, wid = tid >> 5, lane = tid & 31;
    const int b = blockIdx.z, h = blockIdx.y;
    const int q0 = blockIdx.x * 128;
    const size_t base = (size_t)b * SEQL * D + h * 64;
    const int quad = lane >> 3, r = lane & 7;
    const int arow = ((quad & 1) << 3) + r, ak = (quad >> 1) << 3;
    const int brow = ((quad >> 1) << 3) + r, bk = (quad & 1) << 3;
    const int g = lane >> 2, tg = lane & 3;
    const int wq0 = wid << 4;

    // load + split Q tile (128 x 64)
    #pragma unroll
    for (int j = 0; j < 8; j++) {
        int idx = tid + (j << 8);
        int row = idx >> 4, slot = idx & 15;
        float4 q4 = *(const float4*)(Q + base + (size_t)(q0 + row) * D + slot * 4);
        uint2 hi, lo; split2(q4, hi, lo);
        uint32_t off = row * 144 + slot * 8;
        *(uint2*)(smem + AT_QH + off) = hi;
        *(uint2*)(smem + AT_QL + off) = lo;
    }

    float o[8][4];
    #pragma unroll
    for (int j = 0; j < 8; j++)
        #pragma unroll
        for (int q = 0; q < 4; q++) o[j][q] = 0.f;
    float m0r = -1e30f, m1r = -1e30f, l0r = 0.f, l1r = 0.f;

    // prefetch first K/V tile
    float4 kv[8];
    #pragma unroll
    for (int j = 0; j < 4; j++) {
        int idx = tid + (j << 8);
        int row = idx >> 4, slot = idx & 15;
        kv[j]     = *(const float4*)(K + base + (size_t)row * D + slot * 4);
        kv[4 + j] = *(const float4*)(V + base + (size_t)row * D + slot * 4);
    }

    for (int kt = 0; kt < SEQL / 64; kt++) {
        __syncthreads();   // prior tile's ldsm done before overwrite
        #pragma unroll
        for (int j = 0; j < 4; j++) {
            int idx = tid + (j << 8);
            int row = idx >> 4, slot = idx & 15;
            uint2 hi, lo; split2(kv[j], hi, lo);
            uint32_t off = row * 144 + slot * 8;
            *(uint2*)(smem + AT_KH + off) = hi;
            *(uint2*)(smem + AT_KL + off) = lo;
            float4 v = kv[4 + j];
            __nv_bfloat16 vb0 = __float2bfloat16(v.x), vb1 = __float2bfloat16(v.y);
            __nv_bfloat16 vb2 = __float2bfloat16(v.z), vb3 = __float2bfloat16(v.w);
            int dcol = slot * 4;
            *(__nv_bfloat16*)(smem + AT_VT + (dcol + 0) * 144 + row * 2) = vb0;
            *(__nv_bfloat16*)(smem + AT_VT + (dcol + 1) * 144 + row * 2) = vb1;
            *(__nv_bfloat16*)(smem + AT_VT + (dcol + 2) * 144 + row * 2) = vb2;
            *(__nv_bfloat16*)(smem + AT_VT + (dcol + 3) * 144 + row * 2) = vb3;
        }
        __syncthreads();
        if (kt + 1 < SEQL / 64) {
            const size_t koff = base + (size_t)(kt + 1) * 64 * D;
            #pragma unroll
            for (int j = 0; j < 4; j++) {
                int idx = tid + (j << 8);
                int row = idx >> 4, slot = idx & 15;
                kv[j]     = *(const float4*)(K + koff + (size_t)row * D + slot * 4);
                kv[4 + j] = *(const float4*)(V + koff + (size_t)row * D + slot * 4);
            }
        }
        // S = Q @ K^T (split-bf16 3-term)
        float s[8][4];
        #pragma unroll
        for (int j = 0; j < 8; j++)
            #pragma unroll
            for (int q = 0; q < 4; q++) s[j][q] = 0.f;
        #pragma unroll
        for (int kc = 0; kc < 4; kc++) {
            uint32_t ah[4], al[4];
            uint32_t ao = sb + (wq0 + arow) * 144 + ((kc << 4) + ak) * 2;
            ldsm4(ao + AT_QH, ah[0], ah[1], ah[2], ah[3]);
            ldsm4(ao + AT_QL, al[0], al[1], al[2], al[3]);
            #pragma unroll
            for (int jj = 0; jj < 4; jj++) {
                uint32_t bo = sb + ((jj << 4) + brow) * 144 + ((kc << 4) + bk) * 2;
                uint32_t bh0, bh1, bh2, bh3, bl0, bl1, bl2, bl3;
                ldsm4(bo + AT_KH, bh0, bh1, bh2, bh3);
                ldsm4(bo + AT_KL, bl0, bl1, bl2, bl3);
                mma_bf16(s[2 * jj],     ah, bh0, bh1);
                mma_bf16(s[2 * jj],     ah, bl0, bl1);
                mma_bf16(s[2 * jj],     al, bh0, bh1);
                mma_bf16(s[2 * jj + 1], ah, bh2, bh3);
                mma_bf16(s[2 * jj + 1], ah, bl2, bl3);
                mma_bf16(s[2 * jj + 1], al, bh2, bh3);
            }
        }
        // online softmax (rows g and g+8 of warp tile)
        float mx0 = -1e30f, mx1 = -1e30f;
        #pragma unroll
        for (int j = 0; j < 8; j++) {
            s[j][0] *= ATT_SCALE; s[j][1] *= ATT_SCALE;
            s[j][2] *= ATT_SCALE; s[j][3] *= ATT_SCALE;
            mx0 = fmaxf(mx0, fmaxf(s[j][0], s[j][1]));
            mx1 = fmaxf(mx1, fmaxf(s[j][2], s[j][3]));
        }
        mx0 = fmaxf(mx0, __shfl_xor_sync(0xffffffffu, mx0, 1));
        mx0 = fmaxf(mx0, __shfl_xor_sync(0xffffffffu, mx0, 2));
        mx1 = fmaxf(mx1, __shfl_xor_sync(0xffffffffu, mx1, 1));
        mx1 = fmaxf(mx1, __shfl_xor_sync(0xffffffffu, mx1, 2));
        float mn0 = fmaxf(m0r, mx0), mn1 = fmaxf(m1r, mx1);
        float a0 = __expf(m0r - mn0), a1 = __expf(m1r - mn1);
        m0r = mn0; m1r = mn1;
        float rs0 = 0.f, rs1 = 0.f;
        #pragma unroll
        for (int j = 0; j < 8; j++) {
            s[j][0] = __expf(s[j][0] - mn0); s[j][1] = __expf(s[j][1] - mn0);
            s[j][2] = __expf(s[j][2] - mn1); s[j][3] = __expf(s[j][3] - mn1);
            rs0 += s[j][0] + s[j][1];
            rs1 += s[j][2] + s[j][3];
        }
        rs0 += __shfl_xor_sync(0xffffffffu, rs0, 1);
        rs0 += __shfl_xor_sync(0xffffffffu, rs0, 2);
        rs1 += __shfl_xor_sync(0xffffffffu, rs1, 1);
        rs1 += __shfl_xor_sync(0xffffffffu, rs1, 2);
        l0r = l0r * a0 + rs0;
        l1r = l1r * a1 + rs1;
        #pragma unroll
        for (int j = 0; j < 8; j++) {
            o[j][0] *= a0; o[j][1] *= a0; o[j][2] *= a1; o[j][3] *= a1;
        }
        // O += P @ V  (P repacked from C frags to A frags in registers)
        #pragma unroll
        for (int kk = 0; kk < 4; kk++) {
            uint32_t pa[4];
            __nv_bfloat162 t0 = __float22bfloat162_rn(make_float2(s[2 * kk][0], s[2 * kk][1]));
            __nv_bfloat162 t1 = __float22bfloat162_rn(make_float2(s[2 * kk][2], s[2 * kk][3]));
            __nv_bfloat162 t2 = __float22bfloat162_rn(make_float2(s[2 * kk + 1][0], s[2 * kk + 1][1]));
            __nv_bfloat162 t3 = __float22bfloat162_rn(make_float2(s[2 * kk + 1][2], s[2 * kk + 1][3]));
            pa[0] = *(uint32_t*)&t0; pa[1] = *(uint32_t*)&t1;
            pa[2] = *(uint32_t*)&t2; pa[3] = *(uint32_t*)&t3;
            #pragma unroll
            for (int jj = 0; jj < 4; jj++) {
                uint32_t bo = sb + AT_VT + ((jj << 4) + brow) * 144 + ((kk << 4) + bk) * 2;
                uint32_t b0, b1, b2, b3;
                ldsm4(bo, b0, b1, b2, b3);
                mma_bf16(o[2 * jj],     pa, b0, b1);
                mma_bf16(o[2 * jj + 1], pa, b2, b3);
            }
        }
    }
    const float inv0 = 1.0f / l0r, inv1 = 1.0f / l1r;
    #pragma unroll
    for (int j = 0; j < 8; j++) {
        int col = (j << 3) + (tg << 1);
        *(float2*)(O + base + (size_t)(q0 + wq0 + g) * D + col) =
            make_float2(o[j][0] * inv0, o[j][1] * inv0);
        *(float2*)(O + base + (size_t)(q0 + wq0 + g + 8) * D + col) =
            make_float2(o[j][2] * inv1, o[j][3] * inv1);
    }
}

// -------------------- conv along feature dim (3-tap, zero-pad) --------------------
__global__ __launch_bounds__(128) void conv_row(
    float* __restrict__ out, const float* __restrict__ in, const float* __restrict__ w)
{
    __shared__ float rb[D];
    const int row = blockIdx.x, t = threadIdx.x;
    float4 v = *(const float4*)(in + (size_t)row * D + t * 4);
    *(float4*)&rb[t * 4] = v;
    __syncthreads();
    const float w0 = w[0], w1 = w[1], w2 = w[2];
    #pragma unroll
    for (int i = 0; i < 4; i++) {
        int c = t * 4 + i;
        float xm = (c > 0) ? rb[c - 1] : 0.f;
        float xp = (c < D - 1) ? rb[c + 1] : 0.f;
        out[(size_t)row * D + c] = w0 * xm + w1 * rb[c] + w2 * xp;
    }
}

// -------------------- LN(a+b)*g+be; optional hn side-output --------------------
__global__ __launch_bounds__(128) void ln_kernel(
    float* __restrict__ out, const float* __restrict__ a, const float* __restrict__ b,
    const float* __restrict__ g, const float* __restrict__ be,
    float* __restrict__ hn_out, int do_hn)
{
    __shared__ float sh[8];
    const int row = blockIdx.x, t = threadIdx.x;
    float4 av = *(const float4*)(a + (size_t)row * D + t * 4);
    float4 bv = *(const float4*)(b + (size_t)row * D + t * 4);
    float v[4] = {av.x + bv.x, av.y + bv.y, av.z + bv.z, av.w + bv.w};
    float s = v[0] + v[1] + v[2] + v[3];
    float s2 = v[0] * v[0] + v[1] * v[1] + v[2] * v[2] + v[3] * v[3];
    #pragma unroll
    for (int off = 16; off; off >>= 1) {
        s += __shfl_xor_sync(0xffffffffu, s, off);
        s2 += __shfl_xor_sync(0xffffffffu, s2, off);
    }
    if ((t & 31) == 0) { sh[t >> 5] = s; sh[4 + (t >> 5)] = s2; }
    __syncthreads();
    s = sh[0] + sh[1] + sh[2] + sh[3];
    s2 = sh[4] + sh[5] + sh[6] + sh[7];
    const float mean = s * (1.0f / D);
    const float rstd = rsqrtf(s2 * (1.0f / D) - mean * mean + 1e-5f);
    float4 gv = *(const float4*)(g + t * 4);
    float4 bev = *(const float4*)(be + t * 4);
    float4 ov = make_float4((v[0] - mean) * rstd * gv.x + bev.x,
                            (v[1] - mean) * rstd * gv.y + bev.y,
                            (v[2] - mean) * rstd * gv.z + bev.z,
                            (v[3] - mean) * rstd * gv.w + bev.w);
    *(float4*)(out + (size_t)row * D + t * 4) = ov;
    if (do_hn && (row & (SEQL - 1)) == SEQL - 1)
        *(float4*)(hn_out + (size_t)(row >> 10) * D + t * 4) = av;
}

// -------------------- fused LN1 + conv2 --------------------
__global__ __launch_bounds__(128) void ln_conv_kernel(
    float* __restrict__ x1, float* __restrict__ x2c,
    const float* __restrict__ a, const float* __restrict__ b,
    const float* __restrict__ g, const float* __restrict__ be,
    const float* __restrict__ w)
{
    __shared__ float sh[8];
    __shared__ float rb[D];
    const int row = blockIdx.x, t = threadIdx.x;
    float4 av = *(const float4*)(a + (size_t)row * D + t * 4);
    float4 bv = *(const float4*)(b + (size_t)row * D + t * 4);
    float v[4] = {av.x + bv.x, av.y + bv.y, av.z + bv.z, av.w + bv.w};
    float s = v[0] + v[1] + v[2] + v[3];
    float s2 = v[0] * v[0] + v[1] * v[1] + v[2] * v[2] + v[3] * v[3];
    #pragma unroll
    for (int off = 16; off; off >>= 1) {
        s += __shfl_xor_sync(0xffffffffu, s, off);
        s2 += __shfl_xor_sync(0xffffffffu, s2, off);
    }
    if ((t & 31) == 0) { sh[t >> 5] = s; sh[4 + (t >> 5)] = s2; }
    __syncthreads();
    s = sh[0] + sh[1] + sh[2] + sh[3];
    s2 = sh[4] + sh[5] + sh[6] + sh[7];
    const float mean = s * (1.0f / D);
    const float rstd = rsqrtf(s2 * (1.0f / D) - mean * mean + 1e-5f);
    float4 gv = *(const float4*)(g + t * 4);
    float4 bev = *(const float4*)(be + t * 4);
    float y[4];
    y[0] = (v[0] - mean) * rstd * gv.x + bev.x;
    y[1] = (v[1] - mean) * rstd * gv.y + bev.y;
    y[2] = (v[2] - mean) * rstd * gv.z + bev.z;
    y[3] = (v[3] - mean) * rstd * gv.w + bev.w;
    *(float4*)&rb[t * 4] = make_float4(y[0], y[1], y[2], y[3]);
    *(float4*)(x1 + (size_t)row * D + t * 4) = make_float4(y[0], y[1], y[2], y[3]);
    __syncthreads();
    const float w0 = w[0], w1 = w[1], w2 = w[2];
    #pragma unroll
    for (int i = 0; i < 4; i++) {
        int c = t * 4 + i;
        float xm = (c > 0) ? rb[c - 1] : 0.f;
        float xp = (c < D - 1) ? rb[c + 1] : 0.f;
        x2c[(size_t)row * D + c] = w0 * xm + w1 * rb[c] + w2 * xp;
    }
}

// -------------------- launch --------------------
extern "C" void kernel_launch(void* const* d_in, const int* in_sizes, int n_in,
                              void* d_out, int out_size)
{
    const float* input   = (const float*)d_in[0];
    const float* wq_c    = (const float*)d_in[3];
    const float* fc_c    = (const float*)d_in[5];
    const float* wq_g    = (const float*)d_in[6];
    const float* wk_g    = (const float*)d_in[7];
    const float* fc_g    = (const float*)d_in[8];
    const float* wq_x    = (const float*)d_in[9];
    const float* fc_x    = (const float*)d_in[11];
    const float* conv1_w = (const float*)d_in[12];
    const float* conv2_w = (const float*)d_in[13];
    const float* ln1_g = (const float*)d_in[14];
    const float* ln1_b = (const float*)d_in[15];
    const float* ln2_g = (const float*)d_in[16];
    const float* ln2_b = (const float*)d_in[17];
    const float* ln3_g = (const float*)d_in[18];
    const float* ln3_b = (const float*)d_in[19];
    const float* ln4_g = (const float*)d_in[20];
    const float* ln4_b = (const float*)d_in[21];
    const float* mlp_w1 = (const float*)d_in[22];
    const float* mlp_b1 = (const float*)d_in[23];
    const float* mlp_w2 = (const float*)d_in[24];
    const float* mlp_b2 = (const float*)d_in[25];

    float *M1, *M3, *Kg, *Vg, *B0, *B1, *B2, *B3, *B4, *hid;
    cudaGetSymbolAddress((void**)&M1, d_M1);
    cudaGetSymbolAddress((void**)&M3, d_M3);
    cudaGetSymbolAddress((void**)&Kg, d_Kg);
    cudaGetSymbolAddress((void**)&Vg, d_Vg);
    cudaGetSymbolAddress((void**)&B0, d_B0);
    cudaGetSymbolAddress((void**)&B1, d_B1);
    cudaGetSymbolAddress((void**)&B2, d_B2);
    cudaGetSymbolAddress((void**)&B3, d_B3);
    cudaGetSymbolAddress((void**)&B4, d_B4);
    cudaGetSymbolAddress((void**)&hid, d_hid);

    cudaFuncSetAttribute(mma_gemm, cudaFuncAttributeMaxDynamicSharedMemorySize, TCG_SMEM);
    cudaFuncSetAttribute(attn_mma, cudaFuncAttributeMaxDynamicSharedMemorySize, AT_SMEM);

    float* outp = (float*)d_out;
    const size_t out_main = (size_t)N_TOK * D;
    float* hnp = outp + out_main;
    int do_hn = (out_size >= (int)(out_main + BSZ * D)) ? 1 : 0;
    if (!do_hn) hnp = outp;

    const dim3 blk(256);
    const dim3 tg512(D / 128, N_TOK / 128);
    const dim3 tg2048(DFF / 128, N_TOK / 128);
    const dim3 gW(D / 64, D / 64);

    gemm_nn<<<gW, blk>>>(M1, fc_c, wq_c, D, D, D);
    gemm_nn<<<gW, blk>>>(M3, fc_x, wq_x, D, D, D);

    mma_gemm<<<tg512, blk, TCG_SMEM>>>(Kg, input, wk_g, N_TOK, D, D, nullptr, 0);
    mma_gemm<<<tg512, blk, TCG_SMEM>>>(Vg, input, wq_g, N_TOK, D, D, nullptr, 0);

    conv_row<<<N_TOK, 128>>>(B0, input, conv1_w);
    mma_gemm<<<tg512, blk, TCG_SMEM>>>(B1, B0, M1, N_TOK, D, D, nullptr, 0);
    ln_conv_kernel<<<N_TOK, 128>>>(B2, B3, B1, input, ln1_g, ln1_b, conv2_w);

    mma_gemm<<<tg512, blk, TCG_SMEM>>>(B4, B3, wq_g, N_TOK, D, D, nullptr, 0);
    attn_mma<<<dim3(SEQL / 128, 8, BSZ), blk, AT_SMEM>>>(B1, B4, Kg, Vg);
    mma_gemm<<<tg512, blk, TCG_SMEM>>>(B0, B1, fc_g, N_TOK, D, D, nullptr, 0);
    ln_kernel<<<N_TOK, 128>>>(B3, B0, B2, ln2_g, ln2_b, hnp, 0);

    mma_gemm<<<tg512, blk, TCG_SMEM>>>(B2, B3, M3, N_TOK, D, D, nullptr, 0);
    ln_kernel<<<N_TOK, 128>>>(B4, B2, B3, ln3_g, ln3_b, hnp, do_hn);

    mma_gemm<<<tg2048, blk, TCG_SMEM>>>(hid, B4, mlp_w1, N_TOK, DFF, D, mlp_b1, 1);
    mma_gemm<<<tg512, blk, TCG_SMEM>>>(B1, hid, mlp_w2, N_TOK, D, DFF, mlp_b2, 0);
    ln_kernel<<<N_TOK, 128>>>(outp, B1, B4, ln4_g, ln4_b, hnp, 0);
}